// round 5
// baseline (speedup 1.0000x reference)
#include <cuda_runtime.h>
#include <cstdint>

#define S_LEN 512
#define HORIZ 64
#define T_LEN 576   // S_LEN + HORIZ
#define HID   32
#define FEAT  4

// Scratch for deferred attention: h[t] for t = 0..510
__device__ float gH[S_LEN * HID];

// ---------------- packed f32x2 helpers ----------------
#define MUL2(d, a, b) \
    asm("mul.rn.f32x2 %0, %1, %2;" : "=l"(d) : "l"(a), "l"(b))
#define FMA2(d, a, b, c) \
    asm("fma.rn.f32x2 %0, %1, %2, %3;" : "=l"(d) : "l"(a), "l"(b), "l"(c))
#define ADD2(d, a, b) \
    asm("add.rn.f32x2 %0, %1, %2;" : "=l"(d) : "l"(a), "l"(b))
#define PACK2(d, lo, hi) \
    asm("mov.b64 %0, {%1, %2};" : "=l"(d) : "f"(lo), "f"(hi))
#define UNPACK2(lo, hi, v) \
    asm("mov.b64 {%0, %1}, %2;" : "=f"(lo), "=f"(hi) : "l"(v))

__device__ __forceinline__ float tanh_fast(float x) {
    float r; asm("tanh.approx.f32 %0, %1;" : "=f"(r) : "f"(x)); return r;
}

__device__ __forceinline__ float warp_sum(float v) {
#pragma unroll
    for (int d = 16; d; d >>= 1) v += __shfl_xor_sync(0xffffffffu, v, d);
    return v;
}

// Collapsed attention + output head, one warp, lane = hidden unit.
__device__ __forceinline__ void attn_step(
    float h, int lane,
    float A, float B, float C, float D, float C2, float D2,
    float bo, float wmu, float bm, float wsig, float bs,
    float epsv, float* mu_o, float* sig_o, float* samp_o)
{
    float av = __expf(fmaf(A, h, B));
    float rv = av * fmaf(C2, h, D2);
    float pa = av, pr = rv;
#pragma unroll
    for (int d = 1; d < 32; d <<= 1) {
        float ta = __shfl_up_sync(0xffffffffu, pa, d);
        float tr = __shfl_up_sync(0xffffffffu, pr, d);
        if (lane >= d) { pa += ta; pr += tr; }
    }
    float exa = pa - av;          // exclusive prefix of av
    float exr = pr - rv;          // exclusive prefix of r
    float o = tanh_fast(fmaf(C, h, D) + __fdividef(exr, exa + 1e-9f) + bo);
    float pm = o * wmu, ps = o * wsig;
#pragma unroll
    for (int d = 16; d; d >>= 1) {
        pm += __shfl_xor_sync(0xffffffffu, pm, d);
        ps += __shfl_xor_sync(0xffffffffu, ps, d);
    }
    float mu  = pm + bm;
    float sig = __logf(1.0f + __expf(ps + bs)) + 1e-6f;
    *mu_o = mu;
    *sig_o = sig;
    *samp_o = fmaf(sig, epsv, mu);
}

// ---------------------------------------------------------------------------
// Kernel 1: SINGLE warp. Lane j owns hidden unit j and all 4 of its gates,
// packed as two f32x2 accumulators: (i,f) and (g,o). No cross-warp sync at
// all; only one __syncwarp per step for the h store->load hand-off.
//
// Input slot layout per t (48B stride, base 16B-aligned):
//   +0  : (x0,x0)(x1,x1)   <- ld.shared.v2.b64 (16B aligned)
//   +16 : (x2,x2)(x3,x3)   <- ld.shared.v2.b64 (16B aligned)
//   +32 : (yin,yin)        <- ld.shared.b64    (8B aligned ok)
//   +40 : pad
// ---------------------------------------------------------------------------
extern "C" __global__ void __launch_bounds__(32, 1) deepar_seq(
    const float* __restrict__ X,    const float* __restrict__ y,
    const float* __restrict__ Xf,   const float* __restrict__ eps,
    const float* __restrict__ W_ye, const float* __restrict__ b_ye,
    const float* __restrict__ W_ih, const float* __restrict__ W_hh,
    const float* __restrict__ b_ih, const float* __restrict__ b_hh,
    const float* __restrict__ W_ef, const float* __restrict__ b_ef,
    const float* __restrict__ W_av, const float* __restrict__ b_av,
    const float* __restrict__ W_out,const float* __restrict__ b_out,
    const float* __restrict__ W_mu, const float* __restrict__ b_mu,
    const float* __restrict__ W_sig,const float* __restrict__ b_sig,
    float* __restrict__ out)
{
    __shared__ __align__(16) uint64_t sin2[T_LEN * 6];
    __shared__ __align__(16) uint64_t sh2[HID];      // (h_k, h_k) pairs
    __shared__ float se[T_LEN];

    const int j = threadIdx.x;   // lane = hidden unit

    // ---- build duplicated input pairs (slots: x0..x3 at 0..3, yin at 4) ----
    for (int idx = j; idx < T_LEN * 5; idx += 32) {
        int t = idx / 5, f = idx - t * 5;
        float v;
        int slot;
        if (f == 4) {            // yin
            v = (t < S_LEN) ? y[t] : 0.0f;
            slot = 4;
        } else {                 // x features at slots 0..3
            v = (t < S_LEN) ? X[t * FEAT + f] : Xf[(t - S_LEN) * FEAT + f];
            slot = f;
        }
        uint64_t p; PACK2(p, v, v);
        sin2[t * 6 + slot] = p;
    }
    for (int i = j; i < T_LEN; i += 32) se[i] = eps[i];

    // ---- per-lane weights: rows j(i), 32+j(f), 64+j(g), 96+j(o) ----
    // sigmoid gates i,f,o folded by 0.5 so act = fma(0.5, tanh(a'), 0.5).
    const int rI = j, rF = 32 + j, rG = 64 + j, rO = 96 + j;
    uint64_t wif2[32], wgo2[32];
#pragma unroll 8
    for (int k = 0; k < 32; k++) {
        PACK2(wif2[k], 0.5f * W_hh[rI * 32 + k], 0.5f * W_hh[rF * 32 + k]);
        PACK2(wgo2[k],        W_hh[rG * 32 + k], 0.5f * W_hh[rO * 32 + k]);
    }
    // input coefficients: (ug, wx0..wx3) per gate; bias incl b_ye fold
    float ugv[4], bgv[4], wxv[4][4];
#pragma unroll
    for (int g = 0; g < 4; g++) {
        int row = g * 32 + j;
        float u = 0.f, b = b_ih[row] + b_hh[row];
#pragma unroll 8
        for (int k = 0; k < 32; k++) {
            float w = W_ih[row * 36 + 4 + k];
            u = fmaf(w, W_ye[k], u);
            b = fmaf(w, b_ye[k], b);
        }
        ugv[g] = u; bgv[g] = b;
#pragma unroll
        for (int f = 0; f < 4; f++) wxv[g][f] = W_ih[row * 36 + f];
    }
    uint64_t cIF[5], cGO[5], bIF2, bGO2;
    // cIF/cGO[0] = yin coeff ; [1..4] = x0..x3 coeffs
    PACK2(cIF[0], 0.5f * ugv[0], 0.5f * ugv[1]);
    PACK2(cGO[0],        ugv[2], 0.5f * ugv[3]);
#pragma unroll
    for (int f = 0; f < 4; f++) {
        PACK2(cIF[f + 1], 0.5f * wxv[0][f], 0.5f * wxv[1][f]);
        PACK2(cGO[f + 1],        wxv[2][f], 0.5f * wxv[3][f]);
    }
    PACK2(bIF2, 0.5f * bgv[0], 0.5f * bgv[1]);
    PACK2(bGO2,        bgv[2], 0.5f * bgv[3]);

    uint32_t sh_addr, sin_addr;
    asm("{ .reg .u64 t0; cvta.to.shared.u64 t0, %1; cvt.u32.u64 %0, t0; }"
        : "=r"(sh_addr) : "l"(sh2));
    asm("{ .reg .u64 t0; cvta.to.shared.u64 t0, %1; cvt.u32.u64 %0, t0; }"
        : "=r"(sin_addr) : "l"(sin2));

    float c = 0.f;
    {
        uint64_t z; PACK2(z, 0.0f, 0.0f);
        sh2[j] = z;
    }
    __syncwarp();

    // One LSTM step. IN0 is the (yin,yin) pair.
#define LSTM_STEP(T_IDX, IN0, HV_OUT)                                         \
    {                                                                         \
        uint32_t ia = sin_addr + (uint32_t)(T_IDX) * 48u;                     \
        uint64_t p1, p2, p3, p4;                                              \
        asm volatile("ld.shared.v2.b64 {%0, %1}, [%2];"                       \
                     : "=l"(p1), "=l"(p2) : "r"(ia));                         \
        asm volatile("ld.shared.v2.b64 {%0, %1}, [%2];"                       \
                     : "=l"(p3), "=l"(p4) : "r"(ia + 16u));                   \
        uint64_t aIF, aGO;                                                    \
        FMA2(aIF, cIF[0], IN0, bIF2);                                         \
        FMA2(aGO, cGO[0], IN0, bGO2);                                         \
        FMA2(aIF, cIF[1], p1, aIF);  FMA2(aGO, cGO[1], p1, aGO);              \
        FMA2(aIF, cIF[2], p2, aIF);  FMA2(aGO, cGO[2], p2, aGO);              \
        FMA2(aIF, cIF[3], p3, aIF);  FMA2(aGO, cGO[3], p3, aGO);              \
        FMA2(aIF, cIF[4], p4, aIF);  FMA2(aGO, cGO[4], p4, aGO);              \
        uint64_t iA = aIF, iB, iC, iD, gA = aGO, gB, gC, gD;                  \
        {                                                                     \
            uint64_t hp[8];                                                   \
            asm volatile("ld.shared.v2.b64 {%0, %1}, [%2];"                   \
                         : "=l"(hp[0]), "=l"(hp[1]) : "r"(sh_addr + 0u));     \
            asm volatile("ld.shared.v2.b64 {%0, %1}, [%2];"                   \
                         : "=l"(hp[2]), "=l"(hp[3]) : "r"(sh_addr + 16u));    \
            asm volatile("ld.shared.v2.b64 {%0, %1}, [%2];"                   \
                         : "=l"(hp[4]), "=l"(hp[5]) : "r"(sh_addr + 32u));    \
            asm volatile("ld.shared.v2.b64 {%0, %1}, [%2];"                   \
                         : "=l"(hp[6]), "=l"(hp[7]) : "r"(sh_addr + 48u));    \
            FMA2(iA, wif2[0], hp[0], iA);  FMA2(gA, wgo2[0], hp[0], gA);      \
            MUL2(iB, wif2[1], hp[1]);      MUL2(gB, wgo2[1], hp[1]);          \
            MUL2(iC, wif2[2], hp[2]);      MUL2(gC, wgo2[2], hp[2]);          \
            MUL2(iD, wif2[3], hp[3]);      MUL2(gD, wgo2[3], hp[3]);          \
            FMA2(iA, wif2[4], hp[4], iA);  FMA2(gA, wgo2[4], hp[4], gA);      \
            FMA2(iB, wif2[5], hp[5], iB);  FMA2(gB, wgo2[5], hp[5], gB);      \
            FMA2(iC, wif2[6], hp[6], iC);  FMA2(gC, wgo2[6], hp[6], gC);      \
            FMA2(iD, wif2[7], hp[7], iD);  FMA2(gD, wgo2[7], hp[7], gD);      \
            _Pragma("unroll")                                                 \
            for (int q = 1; q < 4; q++) {                                     \
                asm volatile("ld.shared.v2.b64 {%0, %1}, [%2];"               \
                    : "=l"(hp[0]), "=l"(hp[1]) : "r"(sh_addr + 64u * q));     \
                asm volatile("ld.shared.v2.b64 {%0, %1}, [%2];"               \
                    : "=l"(hp[2]), "=l"(hp[3]) : "r"(sh_addr + 64u * q + 16u));\
                asm volatile("ld.shared.v2.b64 {%0, %1}, [%2];"               \
                    : "=l"(hp[4]), "=l"(hp[5]) : "r"(sh_addr + 64u * q + 32u));\
                asm volatile("ld.shared.v2.b64 {%0, %1}, [%2];"               \
                    : "=l"(hp[6]), "=l"(hp[7]) : "r"(sh_addr + 64u * q + 48u));\
                _Pragma("unroll")                                             \
                for (int s = 0; s < 2; s++) {                                 \
                    FMA2(iA, wif2[q*8 + s*4 + 0], hp[s*4 + 0], iA);           \
                    FMA2(gA, wgo2[q*8 + s*4 + 0], hp[s*4 + 0], gA);           \
                    FMA2(iB, wif2[q*8 + s*4 + 1], hp[s*4 + 1], iB);           \
                    FMA2(gB, wgo2[q*8 + s*4 + 1], hp[s*4 + 1], gB);           \
                    FMA2(iC, wif2[q*8 + s*4 + 2], hp[s*4 + 2], iC);           \
                    FMA2(gC, wgo2[q*8 + s*4 + 2], hp[s*4 + 2], gC);           \
                    FMA2(iD, wif2[q*8 + s*4 + 3], hp[s*4 + 3], iD);           \
                    FMA2(gD, wgo2[q*8 + s*4 + 3], hp[s*4 + 3], gD);           \
                }                                                             \
            }                                                                 \
        }                                                                     \
        ADD2(iA, iA, iB); ADD2(iC, iC, iD); ADD2(iA, iA, iC);                 \
        ADD2(gA, gA, gB); ADD2(gC, gC, gD); ADD2(gA, gA, gC);                 \
        float aI_, aF_, aG_, aO_;                                             \
        UNPACK2(aI_, aF_, iA);                                                \
        UNPACK2(aG_, aO_, gA);                                                \
        float gi_ = fmaf(0.5f, tanh_fast(aI_), 0.5f);                         \
        float gf_ = fmaf(0.5f, tanh_fast(aF_), 0.5f);                         \
        float gg_ = tanh_fast(aG_);                                           \
        float go_ = fmaf(0.5f, tanh_fast(aO_), 0.5f);                         \
        c = fmaf(gf_, c, gi_ * gg_);                                          \
        float hv_ = go_ * tanh_fast(c);                                       \
        uint64_t hvp_; PACK2(hvp_, hv_, hv_);                                 \
        asm volatile("st.shared.b64 [%0], %1;"                                \
                     :: "r"(sh_addr + (uint32_t)j * 8u), "l"(hvp_));          \
        __syncwarp();                                                         \
        HV_OUT = hv_;                                                         \
    }

    // ---- segment 1: t = 0..510, yin = y[t] (pre-packed at slot 4) ----
    for (int t = 0; t < S_LEN - 1; t++) {
        uint64_t in0;
        asm volatile("ld.shared.b64 %0, [%1];"
                     : "=l"(in0) : "r"(sin_addr + (uint32_t)t * 48u + 32u));
        float hv;
        LSTM_STEP(t, in0, hv);
        gH[t * 32 + j] = hv;
    }

    // ---- attention scalars (only needed for the tail) ----
    float wef = W_ef[j], bef = b_ef[j], wav = W_av[j];
    float wo1 = W_out[j], wo2 = W_out[32 + j];
    float A  = warp_sum(wef * wav);
    float B  = warp_sum(bef * wav) + b_av[0];
    float C  = warp_sum(wef * wo1);
    float D  = warp_sum(bef * wo1);
    float C2 = warp_sum(wef * wo2);
    float D2 = warp_sum(bef * wo2);
    float bo = b_out[0], bm = b_mu[0], bs = b_sig[0];
    float wmu = W_mu[j], wsig = W_sig[j];

    // ---- segment 2+3: t = 511..575, inline attention, sample feedback ----
    float sample = 0.f;
    for (int t = S_LEN - 1; t < T_LEN; t++) {
        uint64_t in0;
        if (t < S_LEN) {
            asm volatile("ld.shared.b64 %0, [%1];"
                         : "=l"(in0) : "r"(sin_addr + (uint32_t)t * 48u + 32u));
        } else {
            PACK2(in0, sample, sample);
        }
        float hv;
        LSTM_STEP(t, in0, hv);
        float mu, sig;
        attn_step(hv, j, A, B, C, D, C2, D2, bo, wmu, bm, wsig, bs,
                  se[t], &mu, &sig, &sample);
        if (j == 0) {
            out[HORIZ + t]         = mu;
            out[HORIZ + T_LEN + t] = sig;
            if (t < S_LEN - 1 + HORIZ)
                out[t - (S_LEN - 1)] = sample;
        }
    }
#undef LSTM_STEP
}

// ---------------------------------------------------------------------------
// Kernel 2: deferred attention for t = 0..510, one warp per t (all parallel).
// ---------------------------------------------------------------------------
extern "C" __global__ void deepar_att(
    const float* __restrict__ W_ef, const float* __restrict__ b_ef,
    const float* __restrict__ W_av, const float* __restrict__ b_av,
    const float* __restrict__ W_out,const float* __restrict__ b_out,
    const float* __restrict__ W_mu, const float* __restrict__ b_mu,
    const float* __restrict__ W_sig,const float* __restrict__ b_sig,
    float* __restrict__ out)
{
    const int warp = (blockIdx.x * blockDim.x + threadIdx.x) >> 5;
    const int lane = threadIdx.x & 31;
    if (warp >= S_LEN - 1) return;

    float wef = W_ef[lane], bef = b_ef[lane], wav = W_av[lane];
    float wo1 = W_out[lane], wo2 = W_out[32 + lane];
    float A  = warp_sum(wef * wav);
    float B  = warp_sum(bef * wav) + b_av[0];
    float C  = warp_sum(wef * wo1);
    float D  = warp_sum(bef * wo1);
    float C2 = warp_sum(wef * wo2);
    float D2 = warp_sum(bef * wo2);

    float h = gH[warp * 32 + lane];
    float mu, sig, samp;
    attn_step(h, lane, A, B, C, D, C2, D2, b_out[0],
              W_mu[lane], b_mu[0], W_sig[lane], b_sig[0],
              0.f, &mu, &sig, &samp);
    if (lane == 0) {
        out[HORIZ + warp]         = mu;
        out[HORIZ + T_LEN + warp] = sig;
    }
}

extern "C" void kernel_launch(void* const* d_in, const int* in_sizes, int n_in,
                              void* d_out, int out_size)
{
    const float* X     = (const float*)d_in[0];
    const float* y     = (const float*)d_in[1];
    const float* Xf    = (const float*)d_in[2];
    const float* eps   = (const float*)d_in[3];
    const float* W_ye  = (const float*)d_in[4];
    const float* b_ye  = (const float*)d_in[5];
    const float* W_ih  = (const float*)d_in[6];
    const float* W_hh  = (const float*)d_in[7];
    const float* b_ih  = (const float*)d_in[8];
    const float* b_hh  = (const float*)d_in[9];
    const float* W_ef  = (const float*)d_in[10];
    const float* b_ef  = (const float*)d_in[11];
    const float* W_av  = (const float*)d_in[12];
    const float* b_av  = (const float*)d_in[13];
    const float* W_out = (const float*)d_in[14];
    const float* b_out = (const float*)d_in[15];
    const float* W_mu  = (const float*)d_in[16];
    const float* b_mu  = (const float*)d_in[17];
    const float* W_sig = (const float*)d_in[18];
    const float* b_sig = (const float*)d_in[19];
    float* out = (float*)d_out;

    deepar_seq<<<1, 32>>>(X, y, Xf, eps, W_ye, b_ye, W_ih, W_hh, b_ih, b_hh,
                          W_ef, b_ef, W_av, b_av, W_out, b_out,
                          W_mu, b_mu, W_sig, b_sig, out);
    // 511 warps needed; 64 blocks x 256 threads = 512 warps
    deepar_att<<<64, 256>>>(W_ef, b_ef, W_av, b_av, W_out, b_out,
                            W_mu, b_mu, W_sig, b_sig, out);
}

// round 6
// speedup vs baseline: 1.3826x; 1.3826x over previous
#include <cuda_runtime.h>
#include <cstdint>

#define S_LEN 512
#define HORIZ 64
#define T_LEN 576   // S_LEN + HORIZ
#define HID   32
#define FEAT  4

// Scratch for deferred attention: h[t] for t = 0..510
__device__ float gH[S_LEN * HID];

// ---------------- packed f32x2 helpers ----------------
#define MUL2(d, a, b) \
    asm("mul.rn.f32x2 %0, %1, %2;" : "=l"(d) : "l"(a), "l"(b))
#define FMA2(d, a, b, c) \
    asm("fma.rn.f32x2 %0, %1, %2, %3;" : "=l"(d) : "l"(a), "l"(b), "l"(c))
#define ADD2(d, a, b) \
    asm("add.rn.f32x2 %0, %1, %2;" : "=l"(d) : "l"(a), "l"(b))
#define PACK2(d, lo, hi) \
    asm("mov.b64 %0, {%1, %2};" : "=l"(d) : "f"(lo), "f"(hi))
#define UNPACK2(lo, hi, v) \
    asm("mov.b64 {%0, %1}, %2;" : "=f"(lo), "=f"(hi) : "l"(v))

__device__ __forceinline__ float tanh_fast(float x) {
    float r; asm("tanh.approx.f32 %0, %1;" : "=f"(r) : "f"(x)); return r;
}

__device__ __forceinline__ float warp_sum(float v) {
#pragma unroll
    for (int d = 16; d; d >>= 1) v += __shfl_xor_sync(0xffffffffu, v, d);
    return v;
}

// Collapsed attention + output head, one warp, lane = hidden unit.
__device__ __forceinline__ void attn_step(
    float h, int lane,
    float A, float B, float C, float D, float C2, float D2,
    float bo, float wmu, float bm, float wsig, float bs,
    float epsv, float* mu_o, float* sig_o, float* samp_o)
{
    float av = __expf(fmaf(A, h, B));
    float rv = av * fmaf(C2, h, D2);
    float pa = av, pr = rv;
#pragma unroll
    for (int d = 1; d < 32; d <<= 1) {
        float ta = __shfl_up_sync(0xffffffffu, pa, d);
        float tr = __shfl_up_sync(0xffffffffu, pr, d);
        if (lane >= d) { pa += ta; pr += tr; }
    }
    float exa = pa - av;          // exclusive prefix of av
    float exr = pr - rv;          // exclusive prefix of r
    float o = tanh_fast(fmaf(C, h, D) + __fdividef(exr, exa + 1e-9f) + bo);
    float pm = o * wmu, ps = o * wsig;
#pragma unroll
    for (int d = 16; d; d >>= 1) {
        pm += __shfl_xor_sync(0xffffffffu, pm, d);
        ps += __shfl_xor_sync(0xffffffffu, ps, d);
    }
    float mu  = pm + bm;
    float sig = __logf(1.0f + __expf(ps + bs)) + 1e-6f;
    *mu_o = mu;
    *sig_o = sig;
    *samp_o = fmaf(sig, epsv, mu);
}

// ---------------------------------------------------------------------------
// Kernel 1: 4 warps. Warp g owns gate g (i,f,g,o); thread (g,j) owns gate row
// g*32+j. Cell state c_j replicated deterministically in all 4 warps.
// Both per-step syncs are BAR.SYNC (cheaper than WARPSYNC on sm_103a).
// Tail: the h-dot part of step t is issued BEFORE the attn chain of step t-1;
// only the scalar ug*sample term joins afterwards.
// ---------------------------------------------------------------------------
extern "C" __global__ void __launch_bounds__(128, 1) deepar_seq(
    const float* __restrict__ X,    const float* __restrict__ y,
    const float* __restrict__ Xf,   const float* __restrict__ eps,
    const float* __restrict__ W_ye, const float* __restrict__ b_ye,
    const float* __restrict__ W_ih, const float* __restrict__ W_hh,
    const float* __restrict__ b_ih, const float* __restrict__ b_hh,
    const float* __restrict__ W_ef, const float* __restrict__ b_ef,
    const float* __restrict__ W_av, const float* __restrict__ b_av,
    const float* __restrict__ W_out,const float* __restrict__ b_out,
    const float* __restrict__ W_mu, const float* __restrict__ b_mu,
    const float* __restrict__ W_sig,const float* __restrict__ b_sig,
    float* __restrict__ out)
{
    __shared__ __align__(16) float sx[T_LEN * FEAT];
    __shared__ float sy[S_LEN];
    __shared__ float se[T_LEN];
    __shared__ __align__(16) float sh[HID];
    __shared__ __align__(16) float sActT[128];   // transposed: [unit*4 + gate]

    const int tid = threadIdx.x;
    const int g = tid >> 5;      // gate / warp id
    const int j = tid & 31;      // hidden unit / lane

    // ---- preload small inputs to shared ----
    for (int i = tid; i < S_LEN * FEAT; i += 128) sx[i] = X[i];
    for (int i = tid; i < HORIZ * FEAT; i += 128) sx[S_LEN * FEAT + i] = Xf[i];
    for (int i = tid; i < S_LEN; i += 128) sy[i] = y[i];
    for (int i = tid; i < T_LEN; i += 128) se[i] = eps[i];

    // ---- per-thread gate-row weights (packed f32x2 along k) ----
    // sigmoid gates (g != 2): fold the 0.5 pre-scale into ALL row inputs so
    // act = fma(0.5, tanh(a'), 0.5) directly.
    const int row = g * 32 + j;   // torch gate order: i,f,g,o
    const float scl = (g == 2) ? 1.0f : 0.5f;
    uint64_t wh2[16];
    {
        const float2* wr = (const float2*)(W_hh + row * 32);
#pragma unroll
        for (int k = 0; k < 16; k++) {
            float2 v = wr[k];
            PACK2(wh2[k], v.x * scl, v.y * scl);
        }
    }
    float wx0 = W_ih[row * 36 + 0] * scl, wx1 = W_ih[row * 36 + 1] * scl;
    float wx2 = W_ih[row * 36 + 2] * scl, wx3 = W_ih[row * 36 + 3] * scl;
    float ug = 0.f, bg = b_ih[row] + b_hh[row];
#pragma unroll
    for (int k = 0; k < 32; k++) {
        float w = W_ih[row * 36 + 4 + k];
        ug = fmaf(w, W_ye[k], ug);
        bg = fmaf(w, b_ye[k], bg);
    }
    ug *= scl; bg *= scl;
    const float as2 = scl;                     // post-tanh scale
    const float ab2 = (g == 2) ? 0.0f : 0.5f;  // post-tanh bias

    uint32_t sh_addr, sat_addr;
    asm("{ .reg .u64 t0; cvta.to.shared.u64 t0, %1; cvt.u32.u64 %0, t0; }"
        : "=r"(sh_addr) : "l"(sh));
    asm("{ .reg .u64 t0; cvta.to.shared.u64 t0, %1; cvt.u32.u64 %0, t0; }"
        : "=r"(sat_addr) : "l"(sActT));
    const uint32_t sat_my = sat_addr + (uint32_t)(j * 4 + g) * 4u;
    const uint32_t sat_v4 = sat_addr + (uint32_t)j * 16u;

    float c = 0.f;
    if (tid < 32) sh[tid] = 0.f;
    __syncthreads();

    // Partial pre-activation: bias + x-part + h-dot (NO yin term).
#define LSTM_PART(T_IDX, APART_OUT)                                           \
    {                                                                         \
        uint64_t hp[16];                                                      \
        _Pragma("unroll")                                                     \
        for (int q = 0; q < 8; q++)                                           \
            asm volatile("ld.shared.v2.b64 {%0, %1}, [%2];"                   \
                         : "=l"(hp[2*q]), "=l"(hp[2*q+1])                     \
                         : "r"(sh_addr + 16u * q));                           \
        float4 xv = ((const float4*)sx)[T_IDX];                               \
        float base = bg;                                                      \
        base = fmaf(wx0, xv.x, base);                                         \
        base = fmaf(wx1, xv.y, base);                                         \
        base = fmaf(wx2, xv.z, base);                                         \
        base = fmaf(wx3, xv.w, base);                                         \
        uint64_t acc0, acc1, acc2, acc3, bp;                                  \
        PACK2(bp, base, 0.0f);                                                \
        FMA2(acc0, wh2[0], hp[0], bp);                                        \
        MUL2(acc1, wh2[1], hp[1]);                                            \
        MUL2(acc2, wh2[2], hp[2]);                                            \
        MUL2(acc3, wh2[3], hp[3]);                                            \
        _Pragma("unroll")                                                     \
        for (int s = 1; s < 4; s++) {                                         \
            FMA2(acc0, wh2[s*4+0], hp[s*4+0], acc0);                          \
            FMA2(acc1, wh2[s*4+1], hp[s*4+1], acc1);                          \
            FMA2(acc2, wh2[s*4+2], hp[s*4+2], acc2);                          \
            FMA2(acc3, wh2[s*4+3], hp[s*4+3], acc3);                          \
        }                                                                     \
        ADD2(acc0, acc0, acc1);                                               \
        ADD2(acc2, acc2, acc3);                                               \
        ADD2(acc0, acc0, acc2);                                               \
        float lo_, hi_;                                                       \
        UNPACK2(lo_, hi_, acc0);                                              \
        APART_OUT = lo_ + hi_;                                                \
    }

    // Finish: add ug*yin, activate, exchange acts, cell, publish h. Two BARs.
#define LSTM_FINISH(YIN, APART, HV_OUT)                                       \
    {                                                                         \
        float a_ = fmaf(ug, (YIN), (APART));                                  \
        float act_ = fmaf(as2, tanh_fast(a_), ab2);                           \
        asm volatile("st.shared.f32 [%0], %1;" :: "r"(sat_my), "f"(act_));    \
        __syncthreads();                                                      \
        float gi_, gf_, gg_, go_;                                             \
        asm volatile("ld.shared.v4.f32 {%0,%1,%2,%3}, [%4];"                  \
                     : "=f"(gi_), "=f"(gf_), "=f"(gg_), "=f"(go_)             \
                     : "r"(sat_v4));                                          \
        c = fmaf(gf_, c, gi_ * gg_);                                          \
        float hv_ = go_ * tanh_fast(c);                                       \
        if (g == 0)                                                           \
            asm volatile("st.shared.f32 [%0], %1;"                            \
                         :: "r"(sh_addr + (uint32_t)j * 4u), "f"(hv_));       \
        __syncthreads();                                                      \
        HV_OUT = hv_;                                                         \
    }

    // ---- segment 1: t = 0..510, LSTM only, yin = y[t], attn deferred ----
#pragma unroll 2
    for (int t = 0; t < S_LEN - 1; t++) {
        float aPart, hv;
        LSTM_PART(t, aPart);
        LSTM_FINISH(sy[t], aPart, hv);
        if (g == 0) gH[t * 32 + j] = hv;
    }

    // ---- collapsed attention scalars (identical in every warp) ----
    float wef = W_ef[j], bef = b_ef[j], wav = W_av[j];
    float wo1 = W_out[j], wo2 = W_out[32 + j];
    float A  = warp_sum(wef * wav);
    float B  = warp_sum(bef * wav) + b_av[0];
    float C  = warp_sum(wef * wo1);
    float D  = warp_sum(bef * wo1);
    float C2 = warp_sum(wef * wo2);
    float D2 = warp_sum(bef * wo2);
    float bo = b_out[0], bm = b_mu[0], bs = b_sig[0];
    float wmu = W_mu[j], wsig = W_sig[j];

    // ---- t = 511: last observed step ----
    float hv_prev;
    {
        float aPart;
        LSTM_PART(S_LEN - 1, aPart);
        LSTM_FINISH(sy[S_LEN - 1], aPart, hv_prev);
    }

    // ---- t = 512..575: LSTM_PART issued before attn(t-1); sample joins late.
    for (int t = S_LEN; t < T_LEN; t++) {
        float aPart;
        LSTM_PART(t, aPart);                   // independent of sample(t-1)
        float mu, sig, sample;
        attn_step(hv_prev, j, A, B, C, D, C2, D2, bo, wmu, bm, wsig, bs,
                  se[t - 1], &mu, &sig, &sample);
        if (tid == 0) {
            out[HORIZ + (t - 1)]         = mu;
            out[HORIZ + T_LEN + (t - 1)] = sig;
            out[(t - 1) - (S_LEN - 1)]   = sample;   // ypred idx 0..63
        }
        float hv;
        LSTM_FINISH(sample, aPart, hv);
        hv_prev = hv;
    }

    // ---- final attention for t = 575 (mu/sigma only; no ypred slot) ----
    {
        float mu, sig, sample;
        attn_step(hv_prev, j, A, B, C, D, C2, D2, bo, wmu, bm, wsig, bs,
                  se[T_LEN - 1], &mu, &sig, &sample);
        if (tid == 0) {
            out[HORIZ + (T_LEN - 1)]         = mu;
            out[HORIZ + T_LEN + (T_LEN - 1)] = sig;
        }
    }
#undef LSTM_PART
#undef LSTM_FINISH
}

// ---------------------------------------------------------------------------
// Kernel 2: deferred attention for t = 0..510, one warp per t (all parallel).
// ---------------------------------------------------------------------------
extern "C" __global__ void deepar_att(
    const float* __restrict__ W_ef, const float* __restrict__ b_ef,
    const float* __restrict__ W_av, const float* __restrict__ b_av,
    const float* __restrict__ W_out,const float* __restrict__ b_out,
    const float* __restrict__ W_mu, const float* __restrict__ b_mu,
    const float* __restrict__ W_sig,const float* __restrict__ b_sig,
    float* __restrict__ out)
{
    const int warp = (blockIdx.x * blockDim.x + threadIdx.x) >> 5;
    const int lane = threadIdx.x & 31;
    if (warp >= S_LEN - 1) return;

    float wef = W_ef[lane], bef = b_ef[lane], wav = W_av[lane];
    float wo1 = W_out[lane], wo2 = W_out[32 + lane];
    float A  = warp_sum(wef * wav);
    float B  = warp_sum(bef * wav) + b_av[0];
    float C  = warp_sum(wef * wo1);
    float D  = warp_sum(bef * wo1);
    float C2 = warp_sum(wef * wo2);
    float D2 = warp_sum(bef * wo2);

    float h = gH[warp * 32 + lane];
    float mu, sig, samp;
    attn_step(h, lane, A, B, C, D, C2, D2, b_out[0],
              W_mu[lane], b_mu[0], W_sig[lane], b_sig[0],
              0.f, &mu, &sig, &samp);
    if (lane == 0) {
        out[HORIZ + warp]         = mu;
        out[HORIZ + T_LEN + warp] = sig;
    }
}

extern "C" void kernel_launch(void* const* d_in, const int* in_sizes, int n_in,
                              void* d_out, int out_size)
{
    const float* X     = (const float*)d_in[0];
    const float* y     = (const float*)d_in[1];
    const float* Xf    = (const float*)d_in[2];
    const float* eps   = (const float*)d_in[3];
    const float* W_ye  = (const float*)d_in[4];
    const float* b_ye  = (const float*)d_in[5];
    const float* W_ih  = (const float*)d_in[6];
    const float* W_hh  = (const float*)d_in[7];
    const float* b_ih  = (const float*)d_in[8];
    const float* b_hh  = (const float*)d_in[9];
    const float* W_ef  = (const float*)d_in[10];
    const float* b_ef  = (const float*)d_in[11];
    const float* W_av  = (const float*)d_in[12];
    const float* b_av  = (const float*)d_in[13];
    const float* W_out = (const float*)d_in[14];
    const float* b_out = (const float*)d_in[15];
    const float* W_mu  = (const float*)d_in[16];
    const float* b_mu  = (const float*)d_in[17];
    const float* W_sig = (const float*)d_in[18];
    const float* b_sig = (const float*)d_in[19];
    float* out = (float*)d_out;

    deepar_seq<<<1, 128>>>(X, y, Xf, eps, W_ye, b_ye, W_ih, W_hh, b_ih, b_hh,
                           W_ef, b_ef, W_av, b_av, W_out, b_out,
                           W_mu, b_mu, W_sig, b_sig, out);
    // 511 warps needed; 64 blocks x 256 threads = 512 warps
    deepar_att<<<64, 256>>>(W_ef, b_ef, W_av, b_av, W_out, b_out,
                            W_mu, b_mu, W_sig, b_sig, out);
}